// round 3
// baseline (speedup 1.0000x reference)
#include <cuda_runtime.h>
#include <cstdint>
#include <cstddef>

// Problem dims
#define T_STEPS 512
#define BATCH   256
#define DIN     128
#define HDIM    256
#define PDIM    128
#define DH      384            // DIN + HDIM

// Decomposition: 32 clusters x 4 CTAs. Each cluster owns 8 batch rows for all T.
// Rank r owns prototypes [r*32, r*32+32) and hidden cols [r*64, r*64+64) of all 4 gates.
#define CLUSTER 4
#define BT      8
#define NTHR    512

// Shared-memory layout (offsets in floats)
#define OFF_PROTO 0                 // [32][384]   rank's prototype slice
#define OFF_WT    12288             // [128][256]  WT[p][g*64+hl]
#define OFF_C     45056             // [8][384]    combined [x | h]
#define OFF_KT    48128             // [128][8]    kT[p][b] (full P, all ranks write)
#define OFF_PREP  49152             // [2][8][256] gate preact partials (p-halves)
#define OFF_PARTS 53248             // [2][32][8]  RBF dot partials (j-halves)
#define OFF_CX    53760             // [8][64]     cell-state slice (rank-local)
#define OFF_BIAS  54272             // [256]
#define OFF_PN    54528             // [32]        ||proto_p||^2
#define OFF_CN    54560             // [8]         ||c_b||^2
#define SMEM_FLOATS 54568
#define SMEM_BYTES  (SMEM_FLOATS * 4)   // 218272 B

typedef unsigned long long ull;

// ---------------- helpers ----------------

__device__ __forceinline__ uint32_t cvta_shared_u32(const void* p) {
    uint32_t a;
    asm("{ .reg .u64 t; cvta.to.shared.u64 t, %1; cvt.u32.u64 %0, t; }"
        : "=r"(a) : "l"(p));
    return a;
}

__device__ __forceinline__ void stc_f32(uint32_t saddr, uint32_t rank, float v) {
    uint32_t ra;
    asm volatile("mapa.shared::cluster.u32 %0, %1, %2;" : "=r"(ra) : "r"(saddr), "r"(rank));
    asm volatile("st.shared::cluster.f32 [%0], %1;" :: "r"(ra), "f"(v) : "memory");
}

__device__ __forceinline__ ull pack2(float lo, float hi) {
    ull r; asm("mov.b64 %0, {%1, %2};" : "=l"(r) : "f"(lo), "f"(hi)); return r;
}
__device__ __forceinline__ ull ffma2(ull a, ull b, ull c) {
    ull d; asm("fma.rn.f32x2 %0, %1, %2, %3;" : "=l"(d) : "l"(a), "l"(b), "l"(c)); return d;
}
__device__ __forceinline__ ull addf2(ull a, ull b) {
    ull d; asm("add.rn.f32x2 %0, %1, %2;" : "=l"(d) : "l"(a), "l"(b)); return d;
}
__device__ __forceinline__ void unpack2(ull v, float& lo, float& hi) {
    asm("mov.b64 {%0, %1}, %2;" : "=f"(lo), "=f"(hi) : "l"(v));
}

__device__ __forceinline__ float sigf(float x) {
    return __fdividef(1.f, 1.f + __expf(-x));
}
__device__ __forceinline__ float tanhf_fast(float x) {
    float ax = fabsf(x);
    float e  = __expf(-2.f * ax);
    float r  = __fdividef(1.f - e, 1.f + e);
    return copysignf(r, x);
}

// ---------------- kernel ----------------

__global__ void __cluster_dims__(CLUSTER, 1, 1) __launch_bounds__(NTHR, 1)
qlstm_kernel(const float* __restrict__ xin,   const float* __restrict__ proto,
             const float* __restrict__ Wf_p,  const float* __restrict__ bf_p,
             const float* __restrict__ Wi_p,  const float* __restrict__ bi_p,
             const float* __restrict__ Wg_p,  const float* __restrict__ bg_p,
             const float* __restrict__ Wo_p,  const float* __restrict__ bo_p,
             float* __restrict__ out)
{
    extern __shared__ float sm[];
    float* protoS = sm + OFF_PROTO;
    float* WTs    = sm + OFF_WT;
    float* cS     = sm + OFF_C;
    float* kTs    = sm + OFF_KT;
    float* preP   = sm + OFF_PREP;
    float* partS  = sm + OFF_PARTS;
    float* cxS    = sm + OFF_CX;
    float* biasS  = sm + OFF_BIAS;
    float* pnS    = sm + OFF_PN;
    float* cnS    = sm + OFF_CN;

    const int tid  = threadIdx.x;
    const int lane = tid & 31;
    const int w    = tid >> 5;                  // warp 0..15
    const int rank = (int)(blockIdx.x & 3);
    const int B0   = (int)(blockIdx.x >> 2) * BT;
    const uint32_t smem_u32 = cvta_shared_u32(sm);

    // ---------- one-time init ----------
    {
        const float* psrc = proto + (size_t)(rank * 32) * DH;
        for (int i = tid; i < 32 * DH; i += NTHR) protoS[i] = psrc[i];
    }
    {
        #pragma unroll
        for (int g = 0; g < 4; g++) {
            const float* Wg_ = (g == 0) ? Wf_p : (g == 1) ? Wi_p : (g == 2) ? Wg_p : Wo_p;
            for (int i = tid; i < PDIM * 64; i += NTHR) {
                int hl = i >> 7;
                int p  = i & 127;
                WTs[p * 256 + g * 64 + hl] = Wg_[(size_t)(rank * 64 + hl) * PDIM + p];
            }
        }
    }
    if (tid < 64) {
        biasS[        tid] = bf_p[rank * 64 + tid];
        biasS[ 64 +   tid] = bi_p[rank * 64 + tid];
        biasS[128 +   tid] = bg_p[rank * 64 + tid];
        biasS[192 +   tid] = bo_p[rank * 64 + tid];
    }
    for (int i = tid; i < BT * DH; i += NTHR) cS[i]  = 0.f;
    for (int i = tid; i < BT * 64; i += NTHR) cxS[i] = 0.f;
    __syncthreads();

    if (tid < 32) {
        const float4* pr = (const float4*)(protoS + tid * DH);
        float s = 0.f;
        #pragma unroll 8
        for (int q = 0; q < DH / 4; q++) {
            float4 v = pr[q];
            s += v.x * v.x + v.y * v.y + v.z * v.z + v.w * v.w;
        }
        pnS[tid] = s;
    }
    __syncthreads();
    asm volatile("barrier.cluster.arrive.aligned;" ::: "memory");
    asm volatile("barrier.cluster.wait.aligned;"   ::: "memory");

    // prefetch x for t=0: 8*128 floats = 1024 = 512 float2
    float2 xreg = ((const float2*)(xin + (size_t)B0 * DIN))[tid];

    for (int t = 0; t < T_STEPS; t++) {
        // ---------- phase A: combined vector + ||c||^2 ----------
        ((float2*)(cS + (tid >> 6) * DH))[tid & 63] = xreg;
        if (t + 1 < T_STEPS) {
            xreg = ((const float2*)(xin + (size_t)(t + 1) * BATCH * DIN
                                        + (size_t)B0 * DIN))[tid];
        }
        __syncthreads();
        if (w < 8) {
            const float4* cb = (const float4*)(cS + w * DH);
            float4 a0 = cb[lane];
            float4 a1 = cb[32 + lane];
            float4 a2 = cb[64 + lane];
            float s = a0.x * a0.x + a0.y * a0.y + a0.z * a0.z + a0.w * a0.w
                    + a1.x * a1.x + a1.y * a1.y + a1.z * a1.z + a1.w * a1.w
                    + a2.x * a2.x + a2.y * a2.y + a2.z * a2.z + a2.w * a2.w;
            #pragma unroll
            for (int m = 16; m >= 1; m >>= 1)
                s += __shfl_xor_sync(0xffffffffu, s, m);
            if (lane == 0) cnS[w] = s;
        }

        // ---------- phase B: RBF dot partials (j-split halves) ----------
        {
            const int hf  = w >> 3;          // j-half 0/1
            const int pp0 = (w & 7) * 4;     // 4 local protos per warp
            ull acc2[32];
            #pragma unroll
            for (int i = 0; i < 32; i++) acc2[i] = 0ull;

            #pragma unroll
            for (int jc = 0; jc < 3; jc++) {
                const int jj = hf * 96 + jc * 32 + lane;   // float2 index in row
                ull cv2[8], pv2[4];
                #pragma unroll
                for (int b2 = 0; b2 < 8; b2++)
                    cv2[b2] = ((const ull*)(cS + b2 * DH))[jj];
                #pragma unroll
                for (int q = 0; q < 4; q++)
                    pv2[q] = ((const ull*)(protoS + (pp0 + q) * DH))[jj];
                #pragma unroll
                for (int b2 = 0; b2 < 8; b2++) {
                    #pragma unroll
                    for (int q = 0; q < 4; q++)
                        acc2[b2 * 4 + q] = ffma2(cv2[b2], pv2[q], acc2[b2 * 4 + q]);
                }
            }
            // xor-merge: lane l ends with packed partial for idx=l (b=l>>2, q=l&3)
            #pragma unroll
            for (int s5 = 0; s5 < 5; s5++) {
                const int m = 1 << s5;
                const int L = 32 >> s5;
                const bool hi = (lane & m) != 0;
                #pragma unroll
                for (int i = 0; i < (L >> 1); i++) {
                    ull mine = hi ? acc2[2 * i + 1] : acc2[2 * i];
                    ull send = hi ? acc2[2 * i]     : acc2[2 * i + 1];
                    acc2[i] = addf2(mine, __shfl_xor_sync(0xffffffffu, send, m));
                }
            }
            float lo, hi_;
            unpack2(acc2[0], lo, hi_);
            const int b  = lane >> 2;
            const int pl = pp0 + (lane & 3);
            partS[hf * 256 + pl * 8 + b] = lo + hi_;
        }
        __syncthreads();

        // combine halves -> kv -> deliver to all ranks (2 stc per thread)
        {
            const int idx = tid >> 1;        // 0..255
            const int pl  = idx >> 3;        // local proto 0..31
            const int b   = idx & 7;
            const float s  = partS[pl * 8 + b] + partS[256 + pl * 8 + b];
            const float d2 = cnS[b] + pnS[pl] - 2.f * s;
            const float kv = __expf(-d2);    // GAMMA = 1
            const int   pg = rank * 32 + pl;
            const uint32_t a = smem_u32 + (uint32_t)(OFF_KT + pg * 8 + b) * 4u;
            const uint32_t r0 = (uint32_t)(tid & 1) * 2u;
            stc_f32(a, r0, kv);
            stc_f32(a, r0 + 1, kv);
        }
        asm volatile("barrier.cluster.arrive.aligned;" ::: "memory");
        asm volatile("barrier.cluster.wait.aligned;"   ::: "memory");

        // ---------- phase C: gate GEMM partials (p-split halves, f32x2) ----------
        {
            const int hc = tid & 255;        // rank-local gate column
            const int ph = tid >> 8;         // p-half 0/1
            const float bv = (ph == 0) ? biasS[hc] : 0.f;
            ull a0 = pack2(bv, bv), a1 = a0, a2 = a0, a3 = a0;
            const float* wcol = WTs + hc;
            const int p0 = ph * 64;

            #pragma unroll 8
            for (int pp = 0; pp < 64; pp++) {
                const int p = p0 + pp;
                const ulonglong2* kp = (const ulonglong2*)(kTs + p * 8);
                const ulonglong2 k01 = kp[0];
                const ulonglong2 k23 = kp[1];
                const float wv = wcol[p * 256];
                const ull wv2 = pack2(wv, wv);
                a0 = ffma2(k01.x, wv2, a0);
                a1 = ffma2(k01.y, wv2, a1);
                a2 = ffma2(k23.x, wv2, a2);
                a3 = ffma2(k23.y, wv2, a3);
            }
            float lo, hi_;
            float* dst = preP + ph * 2048 + hc;
            unpack2(a0, lo, hi_); dst[0]    = lo; dst[256]  = hi_;
            unpack2(a1, lo, hi_); dst[512]  = lo; dst[768]  = hi_;
            unpack2(a2, lo, hi_); dst[1024] = lo; dst[1280] = hi_;
            unpack2(a3, lo, hi_); dst[1536] = lo; dst[1792] = hi_;
        }
        __syncthreads();

        // ---------- gate combine + state update + outputs ----------
        {
            const int b  = tid >> 6;
            const int hl = tid & 63;
            const float pf  = preP[b * 256 +       hl] + preP[2048 + b * 256 +       hl];
            const float pi_ = preP[b * 256 +  64 + hl] + preP[2048 + b * 256 +  64 + hl];
            const float pg_ = preP[b * 256 + 128 + hl] + preP[2048 + b * 256 + 128 + hl];
            const float po  = preP[b * 256 + 192 + hl] + preP[2048 + b * 256 + 192 + hl];
            const float f  = sigf(pf);
            const float ii = sigf(pi_);
            const float g  = tanhf_fast(pg_);
            const float oo = sigf(po);
            const float cv = f * cxS[b * 64 + hl] + ii * g;
            cxS[b * 64 + hl] = cv;
            const float h = oo * tanhf_fast(cv);

            // deliver h slice into every rank's combined buffer
            const uint32_t a = smem_u32
                + (uint32_t)(OFF_C + b * DH + DIN + rank * 64 + hl) * 4u;
            stc_f32(a, 0, h); stc_f32(a, 1, h); stc_f32(a, 2, h); stc_f32(a, 3, h);

            // release DSMEM stores, then hide global stores inside the barrier
            asm volatile("barrier.cluster.arrive.aligned;" ::: "memory");

            const size_t obase = (size_t)t * BATCH * HDIM
                               + (size_t)(B0 + b) * HDIM + rank * 64 + hl;
            out[obase] = h;
            if (t == T_STEPS - 1) {
                const size_t fbase = (size_t)T_STEPS * BATCH * HDIM
                                   + (size_t)(B0 + b) * HDIM + rank * 64 + hl;
                out[fbase] = h;                                  // hx
                out[fbase + (size_t)BATCH * HDIM] = cv;          // cx
            }
            asm volatile("barrier.cluster.wait.aligned;" ::: "memory");
        }
    }
}

extern "C" void kernel_launch(void* const* d_in, const int* in_sizes, int n_in,
                              void* d_out, int out_size) {
    (void)in_sizes; (void)n_in; (void)out_size;
    const float* xin   = (const float*)d_in[0];
    const float* proto = (const float*)d_in[1];
    const float* Wf    = (const float*)d_in[2];
    const float* bf    = (const float*)d_in[3];
    const float* Wi    = (const float*)d_in[4];
    const float* bi    = (const float*)d_in[5];
    const float* Wg    = (const float*)d_in[6];
    const float* bg    = (const float*)d_in[7];
    const float* Wo    = (const float*)d_in[8];
    const float* bo    = (const float*)d_in[9];
    float* out = (float*)d_out;

    cudaFuncSetAttribute(qlstm_kernel,
                         cudaFuncAttributeMaxDynamicSharedMemorySize, SMEM_BYTES);
    qlstm_kernel<<<(BATCH / BT) * CLUSTER, NTHR, SMEM_BYTES>>>(
        xin, proto, Wf, bf, Wi, bi, Wg, bg, Wo, bo, out);
}